// round 1
// baseline (speedup 1.0000x reference)
#include <cuda_runtime.h>
#include <cstdint>

// Problem constants (fixed by the dataset)
#define NN 100000
#define NE 1600000
#define NG 64
#define C_IN 128
#define C_HID 128
#define C_OUT 64
#define N_CLS 2

// ---------------- scratch (device globals: no allocation allowed) ----------
__device__ float g_H[NN * 128];        // GEMM output h = X @ W
__device__ float g_X[NN * 128];        // layer activations
__device__ float g_dinv[NN];           // 1/sqrt(deg), deg = 1 + indeg
__device__ int   g_cnt[NN];            // in-degree histogram
__device__ int   g_rowoff[NN + 1];     // CSR offsets (dst-sorted)
__device__ int   g_cursor[NN];         // counting-sort cursors
__device__ int   g_ssrc[NE];           // src ids sorted by dst
__device__ float g_sw[NE];             // edge norm weights sorted by dst
__device__ float g_pool[NG * C_OUT];   // per-graph sums
__device__ float g_gcnt[NG];           // per-graph node counts
__device__ int   g_bsums[128];         // scan block sums

// ---------------- preprocessing kernels ------------------------------------
__global__ void k_init() {
    int i = blockIdx.x * blockDim.x + threadIdx.x;
    if (i < NN) g_cnt[i] = 0;
    if (i < NG * C_OUT) g_pool[i] = 0.f;
    if (i < NG) g_gcnt[i] = 0.f;
}

__global__ void k_hist(const int* __restrict__ dst) {
    int e = blockIdx.x * blockDim.x + threadIdx.x;
    if (e < NE) atomicAdd(&g_cnt[dst[e]], 1);
}

__global__ void k_dinv() {
    int i = blockIdx.x * blockDim.x + threadIdx.x;
    if (i < NN) g_dinv[i] = rsqrtf(1.0f + (float)g_cnt[i]);
}

// scan over g_cnt -> g_rowoff (exclusive). 1024 items per block.
__global__ void k_scan1() {
    __shared__ int sm[256];
    int tid = threadIdx.x;
    int base = blockIdx.x * 1024;
    int v[4];
    int ts = 0;
#pragma unroll
    for (int u = 0; u < 4; u++) {
        int idx = base + tid * 4 + u;
        v[u] = (idx < NN) ? g_cnt[idx] : 0;
        ts += v[u];
    }
    sm[tid] = ts;
    __syncthreads();
    // inclusive scan over 256 thread sums
    for (int off = 1; off < 256; off <<= 1) {
        int x = (tid >= off) ? sm[tid - off] : 0;
        __syncthreads();
        sm[tid] += x;
        __syncthreads();
    }
    int run = sm[tid] - ts;  // exclusive prefix for this thread
#pragma unroll
    for (int u = 0; u < 4; u++) {
        int idx = base + tid * 4 + u;
        if (idx < NN) g_rowoff[idx] = run;
        run += v[u];
    }
    if (tid == 255) g_bsums[blockIdx.x] = sm[255];
}

__global__ void k_scan2(int nb) {
    __shared__ int sm[128];
    int tid = threadIdx.x;
    if (tid < nb) sm[tid] = g_bsums[tid];
    __syncthreads();
    if (tid == 0) {
        int acc = 0;
        for (int i = 0; i < nb; i++) { int t = sm[i]; sm[i] = acc; acc += t; }
        g_rowoff[NN] = acc;
    }
    __syncthreads();
    if (tid < nb) g_bsums[tid] = sm[tid];
}

__global__ void k_scan3() {
    int i = blockIdx.x * blockDim.x + threadIdx.x;
    if (i < NN) {
        int v = g_rowoff[i] + g_bsums[i >> 10];
        g_rowoff[i] = v;
        g_cursor[i] = v;
    }
}

__global__ void k_esort(const int* __restrict__ src, const int* __restrict__ dst) {
    int e = blockIdx.x * blockDim.x + threadIdx.x;
    if (e >= NE) return;
    int s = src[e], d = dst[e];
    int p = atomicAdd(&g_cursor[d], 1);
    g_ssrc[p] = s;
    g_sw[p] = g_dinv[s] * g_dinv[d];
}

// ---------------- GEMM: H[n, COUT] = X[n, 128] @ W[128, COUT] ---------------
// Whole W in smem + a 64-row X strip. Packed f32x2 FMAs.
__device__ __forceinline__ void ffma2(unsigned long long& acc,
                                      unsigned long long a,
                                      unsigned long long b) {
    asm("fma.rn.f32x2 %0, %1, %2, %0;" : "+l"(acc) : "l"(a), "l"(b));
}

template <int COUT>
__global__ __launch_bounds__(256) void k_gemm(const float* __restrict__ X,
                                              const float* __restrict__ W,
                                              float* __restrict__ H, int n) {
    constexpr int CIN = 128;
    constexpr int TM = 64;
    constexpr int NPAIR = COUT / 64;  // f32x2 pairs per thread (2 for 128, 1 for 64)
    extern __shared__ float smem[];
    float* Ws = smem;               // CIN * COUT
    float* Xs = smem + CIN * COUT;  // TM * CIN
    int tid = threadIdx.x;

    for (int i = tid; i < CIN * COUT / 4; i += 256)
        ((float4*)Ws)[i] = ((const float4*)W)[i];

    int base = blockIdx.x * TM;
    for (int i = tid; i < TM * CIN / 4; i += 256) {
        int r = i >> 5;
        int c = (i & 31) * 4;
        int gr = base + r;
        float4 v = (gr < n) ? *(const float4*)&X[(size_t)gr * CIN + c]
                            : make_float4(0.f, 0.f, 0.f, 0.f);
        *(float4*)&Xs[r * CIN + c] = v;
    }
    __syncthreads();

    int tx = tid & 31;   // column group
    int ty = tid >> 5;   // row group (8 rows each)

    unsigned long long acc[8][NPAIR];
#pragma unroll
    for (int r = 0; r < 8; r++)
#pragma unroll
        for (int c = 0; c < NPAIR; c++) acc[r][c] = 0ull;

#pragma unroll 4
    for (int k = 0; k < CIN; k++) {
        unsigned long long wv[NPAIR];
        if (NPAIR == 2) {
            ulonglong2 t = *(const ulonglong2*)&Ws[k * COUT + tx * 4];
            wv[0] = t.x; wv[1] = t.y;
        } else {
            wv[0] = *(const unsigned long long*)&Ws[k * COUT + tx * 2];
        }
#pragma unroll
        for (int r = 0; r < 8; r++) {
            float xv = Xs[(ty * 8 + r) * CIN + k];
            unsigned long long xx;
            asm("mov.b64 %0, {%1, %1};" : "=l"(xx) : "r"(__float_as_uint(xv)));
#pragma unroll
            for (int c = 0; c < NPAIR; c++) ffma2(acc[r][c], xx, wv[c]);
        }
    }

#pragma unroll
    for (int r = 0; r < 8; r++) {
        int gr = base + ty * 8 + r;
        if (gr < n) {
            if (NPAIR == 2) {
                ulonglong2 o; o.x = acc[r][0]; o.y = acc[r][1];
                *(ulonglong2*)&H[(size_t)gr * COUT + tx * 4] = o;
            } else {
                *(unsigned long long*)&H[(size_t)gr * COUT + tx * 2] = acc[r][0];
            }
        }
    }
}

// ---------------- aggregation: warp-per-node gather over sorted CSR --------
// out[d] = sum_{e: dst=e->d} H[src]*w + H[d]*dinv[d]^2 + b   (+relu / +pool)
template <int C, bool RELU, bool POOL>
__global__ __launch_bounds__(256) void k_agg(const float* __restrict__ H,
                                             const float* __restrict__ bias,
                                             float* __restrict__ Xo,
                                             const int* __restrict__ batch,
                                             int n) {
    int w = (blockIdx.x * blockDim.x + threadIdx.x) >> 5;
    int lane = threadIdx.x & 31;
    if (w >= n) return;
    int beg = g_rowoff[w];
    int end = g_rowoff[w + 1];

    if (C == 128) {
        float4 acc = make_float4(0.f, 0.f, 0.f, 0.f);
        const float4* H4 = (const float4*)H;
        for (int j = beg; j < end; j++) {
            int s = __ldg(&g_ssrc[j]);
            float wt = __ldg(&g_sw[j]);
            float4 hv = H4[(size_t)s * 32 + lane];
            acc.x = fmaf(wt, hv.x, acc.x);
            acc.y = fmaf(wt, hv.y, acc.y);
            acc.z = fmaf(wt, hv.z, acc.z);
            acc.w = fmaf(wt, hv.w, acc.w);
        }
        float di = g_dinv[w];
        float sl = di * di;
        float4 hd = H4[(size_t)w * 32 + lane];
        float4 bb = *(const float4*)&bias[lane * 4];
        acc.x = fmaf(sl, hd.x, acc.x) + bb.x;
        acc.y = fmaf(sl, hd.y, acc.y) + bb.y;
        acc.z = fmaf(sl, hd.z, acc.z) + bb.z;
        acc.w = fmaf(sl, hd.w, acc.w) + bb.w;
        if (RELU) {
            acc.x = fmaxf(acc.x, 0.f); acc.y = fmaxf(acc.y, 0.f);
            acc.z = fmaxf(acc.z, 0.f); acc.w = fmaxf(acc.w, 0.f);
        }
        *(float4*)&Xo[(size_t)w * 128 + lane * 4] = acc;
    } else {  // C == 64
        float2 acc = make_float2(0.f, 0.f);
        const float2* H2 = (const float2*)H;
        for (int j = beg; j < end; j++) {
            int s = __ldg(&g_ssrc[j]);
            float wt = __ldg(&g_sw[j]);
            float2 hv = H2[(size_t)s * 32 + lane];
            acc.x = fmaf(wt, hv.x, acc.x);
            acc.y = fmaf(wt, hv.y, acc.y);
        }
        float di = g_dinv[w];
        float sl = di * di;
        float2 hd = H2[(size_t)w * 32 + lane];
        float2 bb = *(const float2*)&bias[lane * 2];
        acc.x = fmaf(sl, hd.x, acc.x) + bb.x;
        acc.y = fmaf(sl, hd.y, acc.y) + bb.y;
        if (RELU) { acc.x = fmaxf(acc.x, 0.f); acc.y = fmaxf(acc.y, 0.f); }
        if (POOL) {
            int b = batch[w];
            atomicAdd(&g_pool[b * C_OUT + lane * 2 + 0], acc.x);
            atomicAdd(&g_pool[b * C_OUT + lane * 2 + 1], acc.y);
            if (lane == 0) atomicAdd(&g_gcnt[b], 1.0f);
        } else {
            *(float2*)&Xo[(size_t)w * 64 + lane * 2] = acc;
        }
    }
}

// ---------------- final FC on pooled means ----------------------------------
__global__ void k_fc(const float* __restrict__ Wfc, const float* __restrict__ bfc,
                     float* __restrict__ out) {
    int t = threadIdx.x;  // 128 = 64 graphs * 2 classes
    int g = t >> 1, c = t & 1;
    float s = 0.f;
#pragma unroll
    for (int k = 0; k < C_OUT; k++) s = fmaf(g_pool[g * C_OUT + k], Wfc[k * N_CLS + c], s);
    out[g * N_CLS + c] = s / fmaxf(g_gcnt[g], 1.0f) + bfc[c];
}

// ---------------- launch ----------------------------------------------------
extern "C" void kernel_launch(void* const* d_in, const int* in_sizes, int n_in,
                              void* d_out, int out_size) {
    const float* x    = (const float*)d_in[0];
    const int*   ei   = (const int*)d_in[1];
    const int*   batch= (const int*)d_in[2];
    const float* W1   = (const float*)d_in[3];
    const float* b1   = (const float*)d_in[4];
    const float* W2   = (const float*)d_in[5];
    const float* b2   = (const float*)d_in[6];
    const float* W3   = (const float*)d_in[7];
    const float* b3   = (const float*)d_in[8];
    const float* Wfc  = (const float*)d_in[9];
    const float* bfc  = (const float*)d_in[10];
    float* out = (float*)d_out;

    const int* src = ei;
    const int* dst = ei + NE;

    void *pH = nullptr, *pX = nullptr;
    cudaGetSymbolAddress(&pH, g_H);
    cudaGetSymbolAddress(&pX, g_X);
    float* H = (float*)pH;
    float* X = (float*)pX;

    const int smem128 = (128 * 128 + 64 * 128) * 4;  // 96 KB
    const int smem64  = (128 * 64 + 64 * 128) * 4;   // 64 KB
    cudaFuncSetAttribute(k_gemm<128>, cudaFuncAttributeMaxDynamicSharedMemorySize, smem128);
    cudaFuncSetAttribute(k_gemm<64>,  cudaFuncAttributeMaxDynamicSharedMemorySize, smem64);

    const int NB = (NN + 1023) / 1024;  // 98 scan blocks

    // preprocessing: degree, CSR build
    k_init<<<(NN + 255) / 256, 256>>>();
    k_hist<<<(NE + 255) / 256, 256>>>(dst);
    k_dinv<<<(NN + 255) / 256, 256>>>();
    k_scan1<<<NB, 256>>>();
    k_scan2<<<1, 128>>>(NB);
    k_scan3<<<(NN + 255) / 256, 256>>>();
    k_esort<<<(NE + 255) / 256, 256>>>(src, dst);

    const int gemm_grid = (NN + 63) / 64;
    const int agg_grid  = (NN + 7) / 8;  // 8 warps/block, warp per node

    // layer 1
    k_gemm<128><<<gemm_grid, 256, smem128>>>(x, W1, H, NN);
    k_agg<128, true, false><<<agg_grid, 256>>>(H, b1, X, batch, NN);
    // layer 2
    k_gemm<128><<<gemm_grid, 256, smem128>>>(X, W2, H, NN);
    k_agg<128, true, false><<<agg_grid, 256>>>(H, b2, X, batch, NN);
    // layer 3 (C=64), pooling fused
    k_gemm<64><<<gemm_grid, 256, smem64>>>(X, W3, H, NN);
    k_agg<64, false, true><<<agg_grid, 256>>>(H, b3, nullptr, batch, NN);
    // FC head
    k_fc<<<1, 128>>>(Wfc, bfc, out);
}

// round 3
// speedup vs baseline: 1.1486x; 1.1486x over previous
#include <cuda_runtime.h>
#include <cuda_bf16.h>
#include <cstdint>

// Problem constants (fixed by the dataset)
#define NN 100000
#define NE 1600000
#define NG 64
#define C_IN 128
#define C_HID 128
#define C_OUT 64
#define N_CLS 2

// ---------------- scratch (device globals: no allocation allowed) ----------
__device__ float g_H[NN * 128];        // GEMM output h = X @ W
__device__ float g_X[NN * 128];        // layer activations
__device__ float g_dinv[NN];           // 1/sqrt(deg), deg = 1 + indeg
__device__ int   g_cnt[NN];            // in-degree histogram
__device__ int   g_rowoff[NN + 1];     // CSR offsets (dst-sorted)
__device__ int   g_cursor[NN];         // counting-sort cursors
__device__ int   g_ssrc[NE];           // src ids sorted by dst
__device__ float g_sw[NE];             // edge norm weights sorted by dst
__device__ float g_pool[NG * C_OUT];   // per-graph sums
__device__ float g_gcnt[NG];           // per-graph node counts
__device__ int   g_bsums[128];         // scan block sums

// W packed as bf16 hi/lo in m16n8k16 B-fragment order (u32 granules)
__device__ uint32_t g_W1h[8192], g_W1l[8192];
__device__ uint32_t g_W2h[8192], g_W2l[8192];
__device__ uint32_t g_W3h[4096], g_W3l[4096];

// ---------------- preprocessing kernels ------------------------------------
__global__ void k_init() {
    int i = blockIdx.x * blockDim.x + threadIdx.x;
    if (i < NN) g_cnt[i] = 0;
    if (i < NG * C_OUT) g_pool[i] = 0.f;
    if (i < NG) g_gcnt[i] = 0.f;
}

__global__ void k_hist(const int* __restrict__ dst) {
    int e = blockIdx.x * blockDim.x + threadIdx.x;
    if (e < NE) atomicAdd(&g_cnt[dst[e]], 1);
}

__global__ void k_dinv() {
    int i = blockIdx.x * blockDim.x + threadIdx.x;
    if (i < NN) g_dinv[i] = rsqrtf(1.0f + (float)g_cnt[i]);
}

// Pack W (fp32 row-major [K][N]) into hi/lo bf16 m16n8k16 B-fragment order:
// b-reg layout: for (k, n): j=n>>3, g=n&7, s=k>>4, kk=k&15,
//   tg=(kk>>1)&3, r=kk>>3, h=kk&1, lane=g*4+tg
//   u32 index = ((j*8+s)*32+lane)*2 + r, half h.
__global__ void k_wprep(const float* __restrict__ W1, const float* __restrict__ W2,
                        const float* __restrict__ W3) {
    int i = blockIdx.x * blockDim.x + threadIdx.x;
    if (i >= 2 * 128 * 128 + 128 * 64) return;
    const float* W;
    uint32_t *Wh, *Wl;
    int e, Nout;
    if (i < 16384)      { W = W1; Wh = g_W1h; Wl = g_W1l; e = i;          Nout = 128; }
    else if (i < 32768) { W = W2; Wh = g_W2h; Wl = g_W2l; e = i - 16384;  Nout = 128; }
    else                { W = W3; Wh = g_W3h; Wl = g_W3l; e = i - 32768;  Nout = 64; }
    int k = e / Nout, n = e % Nout;
    float v = W[e];
    __nv_bfloat16 bh = __float2bfloat16_rn(v);
    __nv_bfloat16 bl = __float2bfloat16_rn(v - __bfloat162float(bh));
    int j = n >> 3, g = n & 7, s = k >> 4, kk = k & 15;
    int tg = (kk >> 1) & 3, r = kk >> 3, h = kk & 1, lane = g * 4 + tg;
    int u = ((j * 8 + s) * 32 + lane) * 2 + r;
    ((uint16_t*)Wh)[u * 2 + h] = __bfloat16_as_ushort(bh);
    ((uint16_t*)Wl)[u * 2 + h] = __bfloat16_as_ushort(bl);
}

// scan over g_cnt -> g_rowoff (exclusive). 1024 items per block.
__global__ void k_scan1() {
    __shared__ int sm[256];
    int tid = threadIdx.x;
    int base = blockIdx.x * 1024;
    int v[4];
    int ts = 0;
#pragma unroll
    for (int u = 0; u < 4; u++) {
        int idx = base + tid * 4 + u;
        v[u] = (idx < NN) ? g_cnt[idx] : 0;
        ts += v[u];
    }
    sm[tid] = ts;
    __syncthreads();
    for (int off = 1; off < 256; off <<= 1) {
        int x = (tid >= off) ? sm[tid - off] : 0;
        __syncthreads();
        sm[tid] += x;
        __syncthreads();
    }
    int run = sm[tid] - ts;
#pragma unroll
    for (int u = 0; u < 4; u++) {
        int idx = base + tid * 4 + u;
        if (idx < NN) g_rowoff[idx] = run;
        run += v[u];
    }
    if (tid == 255) g_bsums[blockIdx.x] = sm[255];
}

__global__ void k_scan2(int nb) {
    __shared__ int sm[128];
    int tid = threadIdx.x;
    if (tid < nb) sm[tid] = g_bsums[tid];
    __syncthreads();
    if (tid == 0) {
        int acc = 0;
        for (int i = 0; i < nb; i++) { int t = sm[i]; sm[i] = acc; acc += t; }
        g_rowoff[NN] = acc;
    }
    __syncthreads();
    if (tid < nb) g_bsums[tid] = sm[tid];
}

__global__ void k_scan3() {
    int i = blockIdx.x * blockDim.x + threadIdx.x;
    if (i < NN) {
        int v = g_rowoff[i] + g_bsums[i >> 10];
        g_rowoff[i] = v;
        g_cursor[i] = v;
    }
}

__global__ void k_esort(const int* __restrict__ src, const int* __restrict__ dst) {
    int e = blockIdx.x * blockDim.x + threadIdx.x;
    if (e >= NE) return;
    int s = src[e], d = dst[e];
    int p = atomicAdd(&g_cursor[d], 1);
    g_ssrc[p] = s;
    g_sw[p] = g_dinv[s] * g_dinv[d];
}

// ---------------- HMMA GEMM: H[n, NOUT] = X[n, 128] @ W[128, NOUT] ---------
// Split-bf16: X = Xh + Xl, W = Wh + Wl; D = XhWh + XlWh + XhWl (fp32 acc).
__device__ __forceinline__ void mma_bf16(float* c, const uint32_t* a,
                                         uint32_t b0, uint32_t b1) {
    asm volatile(
        "mma.sync.aligned.m16n8k16.row.col.f32.bf16.bf16.f32 "
        "{%0,%1,%2,%3}, {%4,%5,%6,%7}, {%8,%9}, {%0,%1,%2,%3};"
        : "+f"(c[0]), "+f"(c[1]), "+f"(c[2]), "+f"(c[3])
        : "r"(a[0]), "r"(a[1]), "r"(a[2]), "r"(a[3]), "r"(b0), "r"(b1));
}

// X smem: padded row stride 68 u32 (136 halves) -> conflict-free frag loads.
#define XSTRIDE 68
#define XWORDS (128 * XSTRIDE)   // 8704 u32 per (hi|lo)

template <int NOUT>
__global__ __launch_bounds__(256, 1) void k_mmagemm(const float* __restrict__ X,
                                                    const uint32_t* __restrict__ Wfh,
                                                    const uint32_t* __restrict__ Wfl,
                                                    float* __restrict__ H, int n) {
    extern __shared__ uint32_t smem[];
    uint32_t* Xh = smem;
    uint32_t* Xl = Xh + XWORDS;
    uint32_t* Wh = Xl + XWORDS;
    uint32_t* Wl = Wh + NOUT * 64;

    const int tid = threadIdx.x;
    const int wid = tid >> 5;
    const int lane = tid & 31;
    const int base = blockIdx.x * 128;

    // ---- stage X tile as hi/lo bf16 ----
#pragma unroll 4
    for (int it = 0; it < 16; it++) {
        int chunk = it * 256 + tid;      // 4096 float4 chunks
        int row = chunk >> 5;
        int c4 = chunk & 31;             // float4 index within row
        int grow = base + row;
        float4 v = make_float4(0.f, 0.f, 0.f, 0.f);
        if (grow < n) v = *(const float4*)&X[(size_t)grow * 128 + c4 * 4];
        float f[4] = {v.x, v.y, v.z, v.w};
        uint32_t hp[2], lp[2];
#pragma unroll
        for (int q = 0; q < 2; q++) {
            __nv_bfloat16 h0 = __float2bfloat16_rn(f[2 * q]);
            __nv_bfloat16 h1 = __float2bfloat16_rn(f[2 * q + 1]);
            __nv_bfloat16 l0 = __float2bfloat16_rn(f[2 * q] - __bfloat162float(h0));
            __nv_bfloat16 l1 = __float2bfloat16_rn(f[2 * q + 1] - __bfloat162float(h1));
            hp[q] = ((uint32_t)__bfloat16_as_ushort(h1) << 16) | __bfloat16_as_ushort(h0);
            lp[q] = ((uint32_t)__bfloat16_as_ushort(l1) << 16) | __bfloat16_as_ushort(l0);
        }
        int o = row * XSTRIDE + c4 * 2;
        Xh[o] = hp[0]; Xh[o + 1] = hp[1];
        Xl[o] = lp[0]; Xl[o + 1] = lp[1];
    }
    // ---- copy W fragments into smem ----
    for (int i = tid; i < NOUT * 64; i += 256) {
        Wh[i] = Wfh[i];
        Wl[i] = Wfl[i];
    }
    __syncthreads();

    // warp tiling: NOUT=128 -> 4x2 warps, 32 rows x 64 cols each (MT=2).
    //              NOUT=64  -> 8x1 warps, 16 rows x 64 cols each (MT=1).
    constexpr int MT = (NOUT == 128) ? 2 : 1;
    const int wm = (NOUT == 128) ? (wid >> 1) * 2 : wid;  // first m-tile (16-row units)
    const int ncol0 = (NOUT == 128) ? (wid & 1) * 8 : 0;  // first n-tile (8-col units)
    const int g = lane >> 2;
    const int tg = lane & 3;

    float acc[MT][8][4];
#pragma unroll
    for (int mt = 0; mt < MT; mt++)
#pragma unroll
        for (int j = 0; j < 8; j++)
#pragma unroll
            for (int q = 0; q < 4; q++) acc[mt][j][q] = 0.f;

#pragma unroll
    for (int s = 0; s < 8; s++) {
        uint32_t ah[MT][4], al[MT][4];
#pragma unroll
        for (int mt = 0; mt < MT; mt++) {
            int r0 = (wm + mt) * 16 + g;
            int p0 = s * 8 + tg;
            ah[mt][0] = Xh[r0 * XSTRIDE + p0];
            ah[mt][1] = Xh[(r0 + 8) * XSTRIDE + p0];
            ah[mt][2] = Xh[r0 * XSTRIDE + p0 + 4];
            ah[mt][3] = Xh[(r0 + 8) * XSTRIDE + p0 + 4];
            al[mt][0] = Xl[r0 * XSTRIDE + p0];
            al[mt][1] = Xl[(r0 + 8) * XSTRIDE + p0];
            al[mt][2] = Xl[r0 * XSTRIDE + p0 + 4];
            al[mt][3] = Xl[(r0 + 8) * XSTRIDE + p0 + 4];
        }
#pragma unroll
        for (int j = 0; j < 8; j++) {
            int widx = (((ncol0 + j) * 8 + s) * 32 + lane) * 2;
            uint32_t bh0 = Wh[widx], bh1 = Wh[widx + 1];
            uint32_t bl0 = Wl[widx], bl1 = Wl[widx + 1];
#pragma unroll
            for (int mt = 0; mt < MT; mt++) {
                mma_bf16(acc[mt][j], ah[mt], bh0, bh1);
                mma_bf16(acc[mt][j], al[mt], bh0, bh1);
                mma_bf16(acc[mt][j], ah[mt], bl0, bl1);
            }
        }
    }

    // ---- epilogue: fragment -> gmem (32B sectors per quad) ----
#pragma unroll
    for (int mt = 0; mt < MT; mt++) {
#pragma unroll
        for (int j = 0; j < 8; j++) {
            int row = base + (wm + mt) * 16 + g;
            int col = (ncol0 + j) * 8 + tg * 2;
            if (row < n)
                *(float2*)&H[(size_t)row * NOUT + col] =
                    make_float2(acc[mt][j][0], acc[mt][j][1]);
            if (row + 8 < n)
                *(float2*)&H[(size_t)(row + 8) * NOUT + col] =
                    make_float2(acc[mt][j][2], acc[mt][j][3]);
        }
    }
}

// ---------------- aggregation: warp-per-node gather over sorted CSR --------
template <int C, bool RELU, bool POOL>
__global__ __launch_bounds__(256) void k_agg(const float* __restrict__ H,
                                             const float* __restrict__ bias,
                                             float* __restrict__ Xo,
                                             const int* __restrict__ batch,
                                             int n) {
    int w = (blockIdx.x * blockDim.x + threadIdx.x) >> 5;
    int lane = threadIdx.x & 31;
    if (w >= n) return;
    int beg = g_rowoff[w];
    int end = g_rowoff[w + 1];

    if (C == 128) {
        float4 acc = make_float4(0.f, 0.f, 0.f, 0.f);
        const float4* H4 = (const float4*)H;
        for (int j = beg; j < end; j++) {
            int s = __ldg(&g_ssrc[j]);
            float wt = __ldg(&g_sw[j]);
            float4 hv = H4[(size_t)s * 32 + lane];
            acc.x = fmaf(wt, hv.x, acc.x);
            acc.y = fmaf(wt, hv.y, acc.y);
            acc.z = fmaf(wt, hv.z, acc.z);
            acc.w = fmaf(wt, hv.w, acc.w);
        }
        float di = g_dinv[w];
        float sl = di * di;
        float4 hd = H4[(size_t)w * 32 + lane];
        float4 bb = *(const float4*)&bias[lane * 4];
        acc.x = fmaf(sl, hd.x, acc.x) + bb.x;
        acc.y = fmaf(sl, hd.y, acc.y) + bb.y;
        acc.z = fmaf(sl, hd.z, acc.z) + bb.z;
        acc.w = fmaf(sl, hd.w, acc.w) + bb.w;
        if (RELU) {
            acc.x = fmaxf(acc.x, 0.f); acc.y = fmaxf(acc.y, 0.f);
            acc.z = fmaxf(acc.z, 0.f); acc.w = fmaxf(acc.w, 0.f);
        }
        *(float4*)&Xo[(size_t)w * 128 + lane * 4] = acc;
    } else {  // C == 64
        float2 acc = make_float2(0.f, 0.f);
        const float2* H2 = (const float2*)H;
        for (int j = beg; j < end; j++) {
            int s = __ldg(&g_ssrc[j]);
            float wt = __ldg(&g_sw[j]);
            float2 hv = H2[(size_t)s * 32 + lane];
            acc.x = fmaf(wt, hv.x, acc.x);
            acc.y = fmaf(wt, hv.y, acc.y);
        }
        float di = g_dinv[w];
        float sl = di * di;
        float2 hd = H2[(size_t)w * 32 + lane];
        float2 bb = *(const float2*)&bias[lane * 2];
        acc.x = fmaf(sl, hd.x, acc.x) + bb.x;
        acc.y = fmaf(sl, hd.y, acc.y) + bb.y;
        if (RELU) { acc.x = fmaxf(acc.x, 0.f); acc.y = fmaxf(acc.y, 0.f); }
        if (POOL) {
            int b = batch[w];
            atomicAdd(&g_pool[b * C_OUT + lane * 2 + 0], acc.x);
            atomicAdd(&g_pool[b * C_OUT + lane * 2 + 1], acc.y);
            if (lane == 0) atomicAdd(&g_gcnt[b], 1.0f);
        } else {
            *(float2*)&Xo[(size_t)w * 64 + lane * 2] = acc;
        }
    }
}

// ---------------- final FC on pooled means ----------------------------------
__global__ void k_fc(const float* __restrict__ Wfc, const float* __restrict__ bfc,
                     float* __restrict__ out) {
    int t = threadIdx.x;  // 128 = 64 graphs * 2 classes
    int g = t >> 1, c = t & 1;
    float s = 0.f;
#pragma unroll
    for (int k = 0; k < C_OUT; k++) s = fmaf(g_pool[g * C_OUT + k], Wfc[k * N_CLS + c], s);
    out[g * N_CLS + c] = s / fmaxf(g_gcnt[g], 1.0f) + bfc[c];
}

// ---------------- launch ----------------------------------------------------
extern "C" void kernel_launch(void* const* d_in, const int* in_sizes, int n_in,
                              void* d_out, int out_size) {
    const float* x    = (const float*)d_in[0];
    const int*   ei   = (const int*)d_in[1];
    const int*   batch= (const int*)d_in[2];
    const float* W1   = (const float*)d_in[3];
    const float* b1   = (const float*)d_in[4];
    const float* W2   = (const float*)d_in[5];
    const float* b2   = (const float*)d_in[6];
    const float* W3   = (const float*)d_in[7];
    const float* b3   = (const float*)d_in[8];
    const float* Wfc  = (const float*)d_in[9];
    const float* bfc  = (const float*)d_in[10];
    float* out = (float*)d_out;

    const int* src = ei;
    const int* dst = ei + NE;

    void *pH, *pX, *p1h, *p1l, *p2h, *p2l, *p3h, *p3l;
    cudaGetSymbolAddress(&pH, g_H);
    cudaGetSymbolAddress(&pX, g_X);
    cudaGetSymbolAddress(&p1h, g_W1h);
    cudaGetSymbolAddress(&p1l, g_W1l);
    cudaGetSymbolAddress(&p2h, g_W2h);
    cudaGetSymbolAddress(&p2l, g_W2l);
    cudaGetSymbolAddress(&p3h, g_W3h);
    cudaGetSymbolAddress(&p3l, g_W3l);
    float* H = (float*)pH;
    float* X = (float*)pX;

    const int SMEM128 = (2 * XWORDS + 2 * 128 * 64) * 4;  // 135168 B
    const int SMEM64  = (2 * XWORDS + 2 * 64 * 64) * 4;   // 102400 B
    cudaFuncSetAttribute(k_mmagemm<128>, cudaFuncAttributeMaxDynamicSharedMemorySize, SMEM128);
    cudaFuncSetAttribute(k_mmagemm<64>,  cudaFuncAttributeMaxDynamicSharedMemorySize, SMEM64);

    const int NB = (NN + 1023) / 1024;  // 98 scan blocks

    // preprocessing: degree, CSR build, weight split/pack
    k_init<<<(NN + 255) / 256, 256>>>();
    k_hist<<<(NE + 255) / 256, 256>>>(dst);
    k_wprep<<<(40960 + 255) / 256, 256>>>(W1, W2, W3);
    k_dinv<<<(NN + 255) / 256, 256>>>();
    k_scan1<<<NB, 256>>>();
    k_scan2<<<1, 128>>>(NB);
    k_scan3<<<(NN + 255) / 256, 256>>>();
    k_esort<<<(NE + 255) / 256, 256>>>(src, dst);

    const int gemm_grid = (NN + 127) / 128;  // 782
    const int agg_grid  = (NN + 7) / 8;      // 8 warps/block, warp per node

    // layer 1
    k_mmagemm<128><<<gemm_grid, 256, SMEM128>>>(x, (const uint32_t*)p1h,
                                                (const uint32_t*)p1l, H, NN);
    k_agg<128, true, false><<<agg_grid, 256>>>(H, b1, X, batch, NN);
    // layer 2
    k_mmagemm<128><<<gemm_grid, 256, SMEM128>>>(X, (const uint32_t*)p2h,
                                                (const uint32_t*)p2l, H, NN);
    k_agg<128, true, false><<<agg_grid, 256>>>(H, b2, X, batch, NN);
    // layer 3 (C=64), pooling fused
    k_mmagemm<64><<<gemm_grid, 256, SMEM64>>>(X, (const uint32_t*)p3h,
                                              (const uint32_t*)p3l, H, NN);
    k_agg<64, false, true><<<agg_grid, 256>>>(H, b3, nullptr, batch, NN);
    // FC head
    k_fc<<<1, 128>>>(Wfc, bfc, out);
}